// round 1
// baseline (speedup 1.0000x reference)
#include <cuda_runtime.h>
#include <cuda_bf16.h>
#include <math.h>

// NIQE-style patch statistics + Mahalanobis distance.
// x: (8,4,1056,1056) fp32. PATCH=96, STRIDE=48 -> 21x21 patches per image.
//
// Pass 1: per (b*c, 48-row strip) compute per-column partial sums of
//         x, x^2, gx^2 (horizontal diff^2), gy^2 (vertical diff^2),
//         plus the strip's last gy row (Hlast) for window correction.
// Pass 2: per (b*c, patch-row) combine two strips' column sums in smem,
//         window-sum 21 patches, compute mu/var/grad_mag, write partials.
// Pass 3: reduce partials -> feats(8,12); invert cov[:12,:12]; Mahalanobis;
//         mean over batch -> scalar.

#define IMW 1056
#define IMH 1056
#define NSTRIP 22   // 1056 / 48
#define NPR 21      // patches per dimension
#define NBC 32      // B*C = 8*4
#define P1_THREADS 256
#define NK 5        // ceil(1056/256) columns per thread in pass 1

__device__ float g_colX [NBC * NSTRIP * IMW];
__device__ float g_colX2[NBC * NSTRIP * IMW];
__device__ float g_colG [NBC * NSTRIP * IMW];
__device__ float g_colH [NBC * NSTRIP * IMW];
__device__ float g_Hlast[NBC * NSTRIP * IMW];
__device__ float g_part [NBC * NPR * 3];

__global__ __launch_bounds__(P1_THREADS, 4)
void niqe_pass1(const float* __restrict__ x) {
    const int r   = blockIdx.x;   // strip index 0..21
    const int bc  = blockIdx.y;   // image index 0..31
    const int tid = threadIdx.x;

    __shared__ float buf[IMW];    // current row (for the j+1 neighbor in gx)

    const float* img  = x + (size_t)bc * IMW * IMH;
    const int row0    = r * 48;
    const int nrows   = (r == NSTRIP - 1) ? 48 : 49;  // last strip has no row below

    float aX[NK], aX2[NK], aG[NK], aH[NK], hl[NK], pv[NK];
    #pragma unroll
    for (int k = 0; k < NK; ++k) {
        aX[k] = 0.f; aX2[k] = 0.f; aG[k] = 0.f; aH[k] = 0.f; hl[k] = 0.f; pv[k] = 0.f;
    }

    for (int i = 0; i < nrows; ++i) {
        const float* rowp = img + (size_t)(row0 + i) * IMW;
        float v[NK];
        #pragma unroll
        for (int k = 0; k < NK; ++k) {
            int j = tid + k * P1_THREADS;
            if (j < IMW) { v[k] = rowp[j]; buf[j] = v[k]; }
        }
        __syncthreads();
        #pragma unroll
        for (int k = 0; k < NK; ++k) {
            int j = tid + k * P1_THREADS;
            if (j < IMW) {
                if (i < 48) {
                    aX[k]  += v[k];
                    aX2[k] += v[k] * v[k];
                    if (j < IMW - 1) {
                        float d = buf[j + 1] - v[k];
                        aG[k] += d * d;
                    }
                }
                if (i > 0) {
                    // vertical diff between row (row0+i-1) and (row0+i):
                    // gy row index = row0 + i - 1, belongs to this strip for i=1..48
                    float d  = v[k] - pv[k];
                    float dd = d * d;
                    aH[k] += dd;
                    if (i == 48) hl[k] = dd;   // gy row 48*r+47 (strip's last gy row)
                }
                pv[k] = v[k];
            }
        }
        __syncthreads();
    }

    const size_t base = ((size_t)bc * NSTRIP + r) * IMW;
    #pragma unroll
    for (int k = 0; k < NK; ++k) {
        int j = tid + k * P1_THREADS;
        if (j < IMW) {
            g_colX [base + j] = aX[k];
            g_colX2[base + j] = aX2[k];
            g_colG [base + j] = aG[k];
            g_colH [base + j] = aH[k];
            g_Hlast[base + j] = hl[k];   // 0 for last strip (no row below)
        }
    }
}

__global__ __launch_bounds__(256, 4)
void niqe_pass2() {
    const int pr  = blockIdx.x;   // patch row 0..20
    const int bc  = blockIdx.y;   // image 0..31
    const int tid = threadIdx.x;

    __shared__ float sx[IMW], sx2[IMW], sg[IMW], sh[IMW];
    __shared__ float pres[NPR][3];

    const size_t b0 = ((size_t)bc * NSTRIP + pr) * IMW;
    const size_t b1 = b0 + IMW;

    for (int j = tid; j < IMW; j += 256) {
        sx [j] = g_colX [b0 + j] + g_colX [b1 + j];
        sx2[j] = g_colX2[b0 + j] + g_colX2[b1 + j];
        sg [j] = g_colG [b0 + j] + g_colG [b1 + j];
        // gy window spans 95 rows: strip pr (48 rows) + strip pr+1 minus its last gy row
        sh [j] = g_colH [b0 + j] + g_colH [b1 + j] - g_Hlast[b1 + j];
    }
    __syncthreads();

    const int w = tid >> 5, lane = tid & 31;
    for (int pc = w; pc < NPR; pc += 8) {
        const int c0 = pc * 48;
        float aX = 0.f, aX2 = 0.f, aG = 0.f, aH = 0.f;
        #pragma unroll
        for (int t = 0; t < 3; ++t) {
            int l = lane + t * 32;   // 0..95
            int j = c0 + l;
            aX  += sx[j];
            aX2 += sx2[j];
            aH  += sh[j];
            if (l < 95) aG += sg[j];  // gx window is 95 columns wide
        }
        #pragma unroll
        for (int off = 16; off; off >>= 1) {
            aX  += __shfl_xor_sync(0xffffffffu, aX,  off);
            aX2 += __shfl_xor_sync(0xffffffffu, aX2, off);
            aG  += __shfl_xor_sync(0xffffffffu, aG,  off);
            aH  += __shfl_xor_sync(0xffffffffu, aH,  off);
        }
        if (lane == 0) {
            const float n = 9216.0f;                       // 96*96
            float mu  = aX / n;
            float var = (aX2 - aX * aX / n) / 9215.0f;     // ddof=1
            float gm  = sqrtf((aG + aH) / 9120.0f);        // 96*95
            pres[pc][0] = mu;
            pres[pc][1] = var;
            pres[pc][2] = gm;
        }
    }
    __syncthreads();

    if (tid < 3) {
        float s = 0.f;
        for (int pc = 0; pc < NPR; ++pc) s += pres[pc][tid];
        g_part[((size_t)bc * NPR + pr) * 3 + tid] = s;
    }
}

__global__ __launch_bounds__(288)
void niqe_pass3(const float* __restrict__ mu_p,
                const float* __restrict__ cov_p,
                float* __restrict__ out) {
    const int tid = threadIdx.x;
    __shared__ float feats[8][12];
    __shared__ float A[12][24];      // augmented [cov | I] for Gauss-Jordan
    __shared__ float fcol[12];
    __shared__ float piv;
    __shared__ float dist[8];

    if (tid < 96) {
        int b = tid / 12, fi = tid % 12;
        int s = fi / 4, c = fi % 4;   // feats layout: [mu(4), var(4), gm(4)]
        int bc = b * 4 + c;
        float acc = 0.f;
        for (int pr = 0; pr < NPR; ++pr)
            acc += g_part[((size_t)bc * NPR + pr) * 3 + s];
        feats[b][fi] = acc / 441.0f;
    }
    if (tid < 144) {
        int i = tid / 12, j = tid % 12;
        A[i][j]      = cov_p[i * 36 + j];   // cov_pristine is 36x36, take [:12,:12]
        A[i][12 + j] = (i == j) ? 1.0f : 0.0f;
    }
    __syncthreads();

    // Gauss-Jordan (no pivoting; cov is SPD)
    for (int k = 0; k < 12; ++k) {
        if (tid == 0) piv = 1.0f / A[k][k];
        __syncthreads();
        if (tid < 24) A[k][tid] *= piv;
        __syncthreads();
        if (tid < 12) fcol[tid] = (tid == k) ? 0.0f : A[tid][k];
        __syncthreads();
        {
            int rr = tid / 24, cc = tid % 24;   // blockDim = 288 = 12*24 exactly
            if (rr != k) A[rr][cc] -= fcol[rr] * A[k][cc];
        }
        __syncthreads();
    }

    if (tid < 8) {
        float d[12];
        #pragma unroll
        for (int i = 0; i < 12; ++i) d[i] = feats[tid][i] - mu_p[i];
        float q = 0.f;
        for (int i = 0; i < 12; ++i) {
            float t = 0.f;
            for (int j = 0; j < 12; ++j) t += A[i][12 + j] * d[j];
            q += d[i] * t;
        }
        dist[tid] = sqrtf(q);
    }
    __syncthreads();

    if (tid == 0) {
        float s = 0.f;
        for (int b = 0; b < 8; ++b) s += dist[b];
        out[0] = s * 0.125f;
    }
}

extern "C" void kernel_launch(void* const* d_in, const int* in_sizes, int n_in,
                              void* d_out, int out_size) {
    const float* x     = (const float*)d_in[0];
    const float* mu_p  = (const float*)d_in[1];
    const float* cov_p = (const float*)d_in[2];
    float* out = (float*)d_out;

    niqe_pass1<<<dim3(NSTRIP, NBC), P1_THREADS>>>(x);
    niqe_pass2<<<dim3(NPR, NBC), 256>>>();
    niqe_pass3<<<1, 288>>>(mu_p, cov_p, out);
}

// round 2
// speedup vs baseline: 1.7970x; 1.7970x over previous
#include <cuda_runtime.h>
#include <cuda_bf16.h>
#include <math.h>

// NIQE-style patch statistics + Mahalanobis distance.
// x: (8,4,1056,1056) fp32. PATCH=96, STRIDE=48 -> 21x21 patches per image.
//
// Pass 1 (barrier-free): per (b*c, 24-row strip) each thread owns 4 contiguous
//   columns (LDG.128 + 1 neighbor scalar), accumulates per-column sums of
//   x, x^2, gx^2, gy^2 and the strip's last gy row (Hlast).
// Pass 2: per (b*c, patch-row) combine 4 strips' column sums in smem,
//   window-sum 21 patches, compute mu/var/grad_mag, write partials.
// Pass 3: reduce partials -> feats(8,12); invert cov[:12,:12]; Mahalanobis.

#define IMW 1056
#define NSTRIP 44   // 1056 / 24
#define SROWS 24
#define NPR 21      // patches per dimension
#define NBC 32      // B*C = 8*4
#define P1_T 288
#define NF4 264     // 1056 / 4 float4-columns per row

__device__ __align__(16) float g_colX [NBC * NSTRIP * IMW];
__device__ __align__(16) float g_colX2[NBC * NSTRIP * IMW];
__device__ __align__(16) float g_colG [NBC * NSTRIP * IMW];
__device__ __align__(16) float g_colH [NBC * NSTRIP * IMW];
__device__ __align__(16) float g_Hlast[NBC * NSTRIP * IMW];
__device__ float g_part [NBC * NPR * 3];

__global__ __launch_bounds__(P1_T, 4)
void niqe_pass1(const float* __restrict__ x) {
    const int s   = blockIdx.x;   // strip 0..43
    const int bc  = blockIdx.y;   // image 0..31
    const int t   = threadIdx.x;
    if (t >= NF4) return;         // no barriers anywhere in this kernel
    const int j0  = t * 4;
    const bool nb = (t < NF4 - 1);      // has a right neighbor column
    const float* img = x + (size_t)bc * IMW * IMW + (size_t)s * SROWS * IMW;

    float aX[4] = {0,0,0,0}, aS[4] = {0,0,0,0};
    float aG[4] = {0,0,0,0}, aH[4] = {0,0,0,0}, hl[4] = {0,0,0,0};
    float pv[4];

    // row 0: x-stats + gx only
    {
        const float4 v4 = *(const float4*)(img + j0);
        float v[4] = {v4.x, v4.y, v4.z, v4.w};
        float vn = nb ? __ldg(img + j0 + 4) : 0.f;
        #pragma unroll
        for (int k = 0; k < 4; ++k) { aX[k] += v[k]; aS[k] += v[k]*v[k]; }
        float d;
        d = v[1]-v[0]; aG[0] += d*d;
        d = v[2]-v[1]; aG[1] += d*d;
        d = v[3]-v[2]; aG[2] += d*d;
        if (nb) { d = vn - v[3]; aG[3] += d*d; }
        pv[0]=v[0]; pv[1]=v[1]; pv[2]=v[2]; pv[3]=v[3];
    }
    // rows 1..23: x-stats + gx + gy
    for (int i = 1; i < SROWS; ++i) {
        const float* rp = img + (size_t)i * IMW;
        const float4 v4 = *(const float4*)(rp + j0);
        float v[4] = {v4.x, v4.y, v4.z, v4.w};
        float vn = nb ? __ldg(rp + j0 + 4) : 0.f;
        #pragma unroll
        for (int k = 0; k < 4; ++k) {
            aX[k] += v[k];
            aS[k] += v[k]*v[k];
            float dv = v[k] - pv[k];
            aH[k] += dv*dv;
        }
        float d;
        d = v[1]-v[0]; aG[0] += d*d;
        d = v[2]-v[1]; aG[1] += d*d;
        d = v[3]-v[2]; aG[2] += d*d;
        if (nb) { d = vn - v[3]; aG[3] += d*d; }
        pv[0]=v[0]; pv[1]=v[1]; pv[2]=v[2]; pv[3]=v[3];
    }
    // overlap row (first row of next strip): gy only; this is the strip's
    // last gy row -> also recorded as Hlast for the 95-row window fix.
    if (s != NSTRIP - 1) {
        const float* rp = img + (size_t)SROWS * IMW;
        const float4 v4 = *(const float4*)(rp + j0);
        float v[4] = {v4.x, v4.y, v4.z, v4.w};
        #pragma unroll
        for (int k = 0; k < 4; ++k) {
            float dv = v[k] - pv[k];
            float dd = dv*dv;
            aH[k] += dd;
            hl[k]  = dd;
        }
    }

    const size_t base = ((size_t)bc * NSTRIP + s) * IMW + j0;
    *(float4*)(g_colX  + base) = make_float4(aX[0], aX[1], aX[2], aX[3]);
    *(float4*)(g_colX2 + base) = make_float4(aS[0], aS[1], aS[2], aS[3]);
    *(float4*)(g_colG  + base) = make_float4(aG[0], aG[1], aG[2], aG[3]);
    *(float4*)(g_colH  + base) = make_float4(aH[0], aH[1], aH[2], aH[3]);
    *(float4*)(g_Hlast + base) = make_float4(hl[0], hl[1], hl[2], hl[3]);
}

__global__ __launch_bounds__(256, 4)
void niqe_pass2() {
    const int pr  = blockIdx.x;   // patch row 0..20
    const int bc  = blockIdx.y;   // image 0..31
    const int tid = threadIdx.x;

    __shared__ float sx[IMW], ss[IMW], sg[IMW], sh[IMW];
    __shared__ float pres[NPR][3];

    // patch row pr spans strips 2pr .. 2pr+3 (4 x 24 rows = 96)
    const size_t b = ((size_t)bc * NSTRIP + 2 * pr) * IMW;

    for (int q = tid; q < NF4; q += 256) {
        const int j = 4 * q;
        float4 a, c, d2, e, h4;

        a  = *(const float4*)(g_colX + b + j);
        c  = *(const float4*)(g_colX + b + IMW + j);
        d2 = *(const float4*)(g_colX + b + 2*IMW + j);
        e  = *(const float4*)(g_colX + b + 3*IMW + j);
        sx[j]   = a.x + c.x + d2.x + e.x;
        sx[j+1] = a.y + c.y + d2.y + e.y;
        sx[j+2] = a.z + c.z + d2.z + e.z;
        sx[j+3] = a.w + c.w + d2.w + e.w;

        a  = *(const float4*)(g_colX2 + b + j);
        c  = *(const float4*)(g_colX2 + b + IMW + j);
        d2 = *(const float4*)(g_colX2 + b + 2*IMW + j);
        e  = *(const float4*)(g_colX2 + b + 3*IMW + j);
        ss[j]   = a.x + c.x + d2.x + e.x;
        ss[j+1] = a.y + c.y + d2.y + e.y;
        ss[j+2] = a.z + c.z + d2.z + e.z;
        ss[j+3] = a.w + c.w + d2.w + e.w;

        a  = *(const float4*)(g_colG + b + j);
        c  = *(const float4*)(g_colG + b + IMW + j);
        d2 = *(const float4*)(g_colG + b + 2*IMW + j);
        e  = *(const float4*)(g_colG + b + 3*IMW + j);
        sg[j]   = a.x + c.x + d2.x + e.x;
        sg[j+1] = a.y + c.y + d2.y + e.y;
        sg[j+2] = a.z + c.z + d2.z + e.z;
        sg[j+3] = a.w + c.w + d2.w + e.w;

        // gy window = 95 rows: 4 strips' gy sums minus last strip's last gy row
        a  = *(const float4*)(g_colH + b + j);
        c  = *(const float4*)(g_colH + b + IMW + j);
        d2 = *(const float4*)(g_colH + b + 2*IMW + j);
        e  = *(const float4*)(g_colH + b + 3*IMW + j);
        h4 = *(const float4*)(g_Hlast + b + 3*IMW + j);
        sh[j]   = a.x + c.x + d2.x + e.x - h4.x;
        sh[j+1] = a.y + c.y + d2.y + e.y - h4.y;
        sh[j+2] = a.z + c.z + d2.z + e.z - h4.z;
        sh[j+3] = a.w + c.w + d2.w + e.w - h4.w;
    }
    __syncthreads();

    const int w = tid >> 5, lane = tid & 31;
    for (int pc = w; pc < NPR; pc += 8) {
        const int c0 = pc * 48;
        float aX = 0.f, aS = 0.f, aG = 0.f, aH = 0.f;
        #pragma unroll
        for (int t = 0; t < 3; ++t) {
            int l = lane + t * 32;   // 0..95
            int j = c0 + l;
            aX += sx[j];
            aS += ss[j];
            aH += sh[j];
            if (l < 95) aG += sg[j];  // gx window is 95 columns wide
        }
        #pragma unroll
        for (int off = 16; off; off >>= 1) {
            aX += __shfl_xor_sync(0xffffffffu, aX, off);
            aS += __shfl_xor_sync(0xffffffffu, aS, off);
            aG += __shfl_xor_sync(0xffffffffu, aG, off);
            aH += __shfl_xor_sync(0xffffffffu, aH, off);
        }
        if (lane == 0) {
            const float n = 9216.0f;                      // 96*96
            pres[pc][0] = aX / n;                         // mu
            pres[pc][1] = (aS - aX * aX / n) / 9215.0f;   // var, ddof=1
            pres[pc][2] = sqrtf((aG + aH) / 9120.0f);     // grad mag, 96*95
        }
    }
    __syncthreads();

    if (tid < 3) {
        float s = 0.f;
        for (int pc = 0; pc < NPR; ++pc) s += pres[pc][tid];
        g_part[((size_t)bc * NPR + pr) * 3 + tid] = s;
    }
}

__global__ __launch_bounds__(288)
void niqe_pass3(const float* __restrict__ mu_p,
                const float* __restrict__ cov_p,
                float* __restrict__ out) {
    const int tid = threadIdx.x;
    __shared__ float feats[8][12];
    __shared__ float A[12][24];      // augmented [cov | I] for Gauss-Jordan
    __shared__ float fcol[12];
    __shared__ float piv;
    __shared__ float dist[8];

    if (tid < 96) {
        int b = tid / 12, fi = tid % 12;
        int s = fi / 4, c = fi % 4;   // feats layout: [mu(4), var(4), gm(4)]
        int bc = b * 4 + c;
        float acc = 0.f;
        for (int pr = 0; pr < NPR; ++pr)
            acc += g_part[((size_t)bc * NPR + pr) * 3 + s];
        feats[b][fi] = acc / 441.0f;
    }
    if (tid < 144) {
        int i = tid / 12, j = tid % 12;
        A[i][j]      = cov_p[i * 36 + j];   // cov_pristine is 36x36, take [:12,:12]
        A[i][12 + j] = (i == j) ? 1.0f : 0.0f;
    }
    __syncthreads();

    // Gauss-Jordan (no pivoting; cov is SPD)
    for (int k = 0; k < 12; ++k) {
        if (tid == 0) piv = 1.0f / A[k][k];
        __syncthreads();
        if (tid < 24) A[k][tid] *= piv;
        __syncthreads();
        if (tid < 12) fcol[tid] = (tid == k) ? 0.0f : A[tid][k];
        __syncthreads();
        {
            int rr = tid / 24, cc = tid % 24;   // blockDim = 288 = 12*24 exactly
            if (rr != k) A[rr][cc] -= fcol[rr] * A[k][cc];
        }
        __syncthreads();
    }

    if (tid < 8) {
        float d[12];
        #pragma unroll
        for (int i = 0; i < 12; ++i) d[i] = feats[tid][i] - mu_p[i];
        float q = 0.f;
        for (int i = 0; i < 12; ++i) {
            float t = 0.f;
            for (int j = 0; j < 12; ++j) t += A[i][12 + j] * d[j];
            q += d[i] * t;
        }
        dist[tid] = sqrtf(q);
    }
    __syncthreads();

    if (tid == 0) {
        float s = 0.f;
        for (int b = 0; b < 8; ++b) s += dist[b];
        out[0] = s * 0.125f;
    }
}

extern "C" void kernel_launch(void* const* d_in, const int* in_sizes, int n_in,
                              void* d_out, int out_size) {
    const float* x     = (const float*)d_in[0];
    const float* mu_p  = (const float*)d_in[1];
    const float* cov_p = (const float*)d_in[2];
    float* out = (float*)d_out;

    niqe_pass1<<<dim3(NSTRIP, NBC), P1_T>>>(x);
    niqe_pass2<<<dim3(NPR, NBC), 256>>>();
    niqe_pass3<<<1, 288>>>(mu_p, cov_p, out);
}

// round 3
// speedup vs baseline: 2.2033x; 1.2261x over previous
#include <cuda_runtime.h>
#include <cuda_bf16.h>
#include <math.h>

// NIQE-style patch statistics + Mahalanobis distance.
// x: (8,4,1056,1056) fp32. PATCH=96, STRIDE=48 -> 21x21 patches per image.
//
// Pass 1: per (b*c, 24-row strip) accumulate per-column sums of x, x^2,
//   gx^2, gy^2 (+ last gy row), then reduce to per-48-column SEGMENT sums
//   in smem before writing (0.74 MB intermediate instead of 30 MB).
//   Patch windows (96 cols @ stride 48) are exactly 2 segments; gx's 95-col
//   window = 2 segments - colG[48m+47] (stored as bndG); gy's 95-row window
//   = 4 strips - last strip's last gy row (segHl).
// Pass 2: 1 block per image; 441 threads each compute one patch's
//   mu/var/grad_mag from segment sums; tree-reduce -> per-image feature sums.
// Pass 3: feats(8,12); invert cov[:12,:12]; Mahalanobis; mean.

#define IMW 1056
#define NSTRIP 44   // 1056 / 24
#define SROWS 24
#define NPR 21
#define NBC 32
#define P1_T 288
#define NF4 264     // 1056/4 float4-columns
#define NSEG 22     // 1056/48 segments
#define SEGSTR (6 * NSEG)   // floats per (bc,strip): X,X2,G,H,Hl,bndG

__device__ float g_seg [NBC * NSTRIP * SEGSTR];
__device__ float g_feat[NBC * 3];

__global__ __launch_bounds__(P1_T, 4)
void niqe_pass1(const float* __restrict__ x) {
    const int s   = blockIdx.x;   // strip 0..43
    const int bc  = blockIdx.y;   // image 0..31
    const int t   = threadIdx.x;

    __shared__ float red[5][NF4];
    __shared__ float bnd[NSEG];

    float aX[4] = {0,0,0,0}, aS[4] = {0,0,0,0};
    float aG[4] = {0,0,0,0}, aH[4] = {0,0,0,0}, hl[4] = {0,0,0,0};

    if (t < NF4) {
        const int j0  = t * 4;
        const bool nb = (t < NF4 - 1);
        const float* img = x + (size_t)bc * IMW * IMW + (size_t)s * SROWS * IMW;
        float pv[4];

        // row 0: x-stats + gx only
        {
            const float4 v4 = *(const float4*)(img + j0);
            float v[4] = {v4.x, v4.y, v4.z, v4.w};
            float vn = nb ? __ldg(img + j0 + 4) : 0.f;
            #pragma unroll
            for (int k = 0; k < 4; ++k) { aX[k] += v[k]; aS[k] += v[k]*v[k]; }
            float d;
            d = v[1]-v[0]; aG[0] += d*d;
            d = v[2]-v[1]; aG[1] += d*d;
            d = v[3]-v[2]; aG[2] += d*d;
            d = vn - v[3]; aG[3] += d*d;      // vn=0 & unused for t=NF4-1 is fine? no:
            if (!nb) aG[3] = 0.f;             // keep col-1055 gx = 0 exactly
            pv[0]=v[0]; pv[1]=v[1]; pv[2]=v[2]; pv[3]=v[3];
        }
        // rows 1..23
        #pragma unroll 4
        for (int i = 1; i < SROWS; ++i) {
            const float* rp = img + (size_t)i * IMW;
            const float4 v4 = *(const float4*)(rp + j0);
            float v[4] = {v4.x, v4.y, v4.z, v4.w};
            float vn = nb ? __ldg(rp + j0 + 4) : 0.f;
            #pragma unroll
            for (int k = 0; k < 4; ++k) {
                aX[k] += v[k];
                aS[k] += v[k]*v[k];
                float dv = v[k] - pv[k];
                aH[k] += dv*dv;
            }
            float d;
            d = v[1]-v[0]; aG[0] += d*d;
            d = v[2]-v[1]; aG[1] += d*d;
            d = v[3]-v[2]; aG[2] += d*d;
            if (nb) { d = vn - v[3]; aG[3] += d*d; }
            pv[0]=v[0]; pv[1]=v[1]; pv[2]=v[2]; pv[3]=v[3];
        }
        // overlap row (first row of next strip): gy only -> also Hlast
        if (s != NSTRIP - 1) {
            const float* rp = img + (size_t)SROWS * IMW;
            const float4 v4 = *(const float4*)(rp + j0);
            float v[4] = {v4.x, v4.y, v4.z, v4.w};
            #pragma unroll
            for (int k = 0; k < 4; ++k) {
                float dv = v[k] - pv[k];
                float dd = dv*dv;
                aH[k] += dd;
                hl[k]  = dd;
            }
        }

        red[0][t] = aX[0]+aX[1]+aX[2]+aX[3];
        red[1][t] = aS[0]+aS[1]+aS[2]+aS[3];
        red[2][t] = aG[0]+aG[1]+aG[2]+aG[3];
        red[3][t] = aH[0]+aH[1]+aH[2]+aH[3];
        red[4][t] = hl[0]+hl[1]+hl[2]+hl[3];
        if ((t % 12) == 11) bnd[t / 12] = aG[3];  // colG at col 48m+47
    }
    __syncthreads();

    float* out = g_seg + ((size_t)bc * NSTRIP + s) * SEGSTR;
    if (t < 5 * NSEG) {
        const int stat = t / NSEG, m = t % NSEG;
        float acc = 0.f;
        #pragma unroll
        for (int q = 0; q < 12; ++q) acc += red[stat][12 * m + q];
        out[stat * NSEG + m] = acc;
    } else if (t < 6 * NSEG) {
        out[t] = bnd[t - 5 * NSEG];   // stat 5 = bndG
    }
}

__global__ __launch_bounds__(512)
void niqe_pass2() {
    const int bc  = blockIdx.x;
    const int tid = threadIdx.x;
    __shared__ float r0[512], r1[512], r2[512];

    float mu = 0.f, var = 0.f, gm = 0.f;
    if (tid < NPR * NPR) {
        const int pr = tid / NPR, pc = tid % NPR;
        const float* base = g_seg + ((size_t)bc * NSTRIP + 2 * pr) * SEGSTR;
        float X = 0.f, S = 0.f, G = 0.f, H = 0.f;
        #pragma unroll
        for (int s4 = 0; s4 < 4; ++s4) {
            const float* seg = base + s4 * SEGSTR;
            X += seg[0*NSEG + pc] + seg[0*NSEG + pc + 1];
            S += seg[1*NSEG + pc] + seg[1*NSEG + pc + 1];
            G += seg[2*NSEG + pc] + seg[2*NSEG + pc + 1] - seg[5*NSEG + pc + 1];
            H += seg[3*NSEG + pc] + seg[3*NSEG + pc + 1];
        }
        const float* seg3 = base + 3 * SEGSTR;
        H -= seg3[4*NSEG + pc] + seg3[4*NSEG + pc + 1];  // drop last gy row
        mu  = X / 9216.0f;
        var = (S - X * X / 9216.0f) / 9215.0f;
        gm  = sqrtf((G + H) / 9120.0f);
    }
    r0[tid] = mu; r1[tid] = var; r2[tid] = gm;
    __syncthreads();
    #pragma unroll
    for (int off = 256; off; off >>= 1) {
        if (tid < off) {
            r0[tid] += r0[tid + off];
            r1[tid] += r1[tid + off];
            r2[tid] += r2[tid + off];
        }
        __syncthreads();
    }
    if (tid == 0) {
        g_feat[bc * 3 + 0] = r0[0];
        g_feat[bc * 3 + 1] = r1[0];
        g_feat[bc * 3 + 2] = r2[0];
    }
}

__global__ __launch_bounds__(288)
void niqe_pass3(const float* __restrict__ mu_p,
                const float* __restrict__ cov_p,
                float* __restrict__ out) {
    const int tid = threadIdx.x;
    __shared__ float feats[8][12];
    __shared__ float A[12][24];
    __shared__ float fcol[12];
    __shared__ float piv;
    __shared__ float dist[8];

    if (tid < 96) {
        int b = tid / 12, fi = tid % 12;
        int s = fi / 4, c = fi % 4;   // feats layout: [mu(4), var(4), gm(4)]
        feats[b][fi] = g_feat[(b * 4 + c) * 3 + s] / 441.0f;
    }
    if (tid < 144) {
        int i = tid / 12, j = tid % 12;
        A[i][j]      = cov_p[i * 36 + j];
        A[i][12 + j] = (i == j) ? 1.0f : 0.0f;
    }
    __syncthreads();

    for (int k = 0; k < 12; ++k) {
        if (tid == 0) piv = 1.0f / A[k][k];
        __syncthreads();
        if (tid < 24) A[k][tid] *= piv;
        __syncthreads();
        if (tid < 12) fcol[tid] = (tid == k) ? 0.0f : A[tid][k];
        __syncthreads();
        {
            int rr = tid / 24, cc = tid % 24;
            if (rr != k) A[rr][cc] -= fcol[rr] * A[k][cc];
        }
        __syncthreads();
    }

    if (tid < 8) {
        float d[12];
        #pragma unroll
        for (int i = 0; i < 12; ++i) d[i] = feats[tid][i] - mu_p[i];
        float q = 0.f;
        for (int i = 0; i < 12; ++i) {
            float t = 0.f;
            for (int j = 0; j < 12; ++j) t += A[i][12 + j] * d[j];
            q += d[i] * t;
        }
        dist[tid] = sqrtf(q);
    }
    __syncthreads();

    if (tid == 0) {
        float s = 0.f;
        for (int b = 0; b < 8; ++b) s += dist[b];
        out[0] = s * 0.125f;
    }
}

extern "C" void kernel_launch(void* const* d_in, const int* in_sizes, int n_in,
                              void* d_out, int out_size) {
    const float* x     = (const float*)d_in[0];
    const float* mu_p  = (const float*)d_in[1];
    const float* cov_p = (const float*)d_in[2];
    float* out = (float*)d_out;

    niqe_pass1<<<dim3(NSTRIP, NBC), P1_T>>>(x);
    niqe_pass2<<<NBC, 512>>>();
    niqe_pass3<<<1, 288>>>(mu_p, cov_p, out);
}

// round 7
// speedup vs baseline: 2.3629x; 1.0724x over previous
#include <cuda_runtime.h>
#include <cuda_bf16.h>
#include <math.h>

// NIQE-style patch statistics + Mahalanobis distance.
// x: (8,4,1056,1056) fp32. PATCH=96, STRIDE=48 -> 21x21 patches per image.
//
// Pass 1: per (b*c, 24-row strip), scalar per-thread accumulators (segment
//   sums never need per-column data; only bndG = gx^2 column at 48m+47 is
//   kept separate). Unconditional clamped loads + unroll-8 row loop so
//   ptxas can batch LDGs deep (latency-bound fix).
// Pass 2 (+3 fused): 1 block per image computes per-image feature sums from
//   segment sums; the last block to finish (atomic counter) runs the 12x12
//   covariance inverse + Mahalanobis + mean. Counter self-resets per launch.

#define IMW 1056
#define NSTRIP 44   // 1056 / 24
#define SROWS 24
#define NPR 21
#define NBC 32
#define P1_T 288
#define NF4 264     // 1056/4 float4-columns
#define NSEG 22     // 1056/48 segments
#define SEGSTR (6 * NSEG)   // per (bc,strip): X,X2,G,H,Hl,bndG

__device__ float g_seg [NBC * NSTRIP * SEGSTR];
__device__ float g_feat[NBC * 3];
__device__ unsigned int g_ctr = 0;

__global__ __launch_bounds__(P1_T, 4)
void niqe_pass1(const float* __restrict__ x) {
    const int s   = blockIdx.x;   // strip 0..43
    const int bc  = blockIdx.y;   // image 0..31
    const int t   = threadIdx.x;

    __shared__ float red[5][NF4];
    __shared__ float bnd[NSEG];

    float aX = 0.f, aS = 0.f, aG = 0.f, aG3 = 0.f, aH = 0.f, hl = 0.f;

    if (t < NF4) {
        const int j0   = t * 4;
        const int offn = (t < NF4 - 1) ? 4 : 3;   // clamped: edge thread gets d3 = 0 exactly
        const float* img = x + (size_t)bc * IMW * IMW + (size_t)s * SROWS * IMW;
        float pv0, pv1, pv2, pv3;

        // row 0: x-stats + gx (no gy)
        {
            const float4 v = *(const float4*)(img + j0);
            const float vn = img[j0 + offn];
            aX += v.x + v.y + v.z + v.w;
            aS += v.x*v.x + v.y*v.y + v.z*v.z + v.w*v.w;
            float d0 = v.y - v.x, d1 = v.z - v.y, d2 = v.w - v.z, d3 = vn - v.w;
            aG  += d0*d0 + d1*d1 + d2*d2;
            aG3 += d3*d3;
            pv0 = v.x; pv1 = v.y; pv2 = v.z; pv3 = v.w;
        }
        // rows 1..23: all stats; unroll 8, unconditional loads
        #pragma unroll 8
        for (int i = 1; i < SROWS; ++i) {
            const float* rp = img + (size_t)i * IMW;
            const float4 v = *(const float4*)(rp + j0);
            const float vn = rp[j0 + offn];
            aX += v.x + v.y + v.z + v.w;
            aS += v.x*v.x + v.y*v.y + v.z*v.z + v.w*v.w;
            float e0 = v.x - pv0, e1 = v.y - pv1, e2 = v.z - pv2, e3 = v.w - pv3;
            aH += e0*e0 + e1*e1 + e2*e2 + e3*e3;
            float d0 = v.y - v.x, d1 = v.z - v.y, d2 = v.w - v.z, d3 = vn - v.w;
            aG  += d0*d0 + d1*d1 + d2*d2;
            aG3 += d3*d3;
            pv0 = v.x; pv1 = v.y; pv2 = v.z; pv3 = v.w;
        }
        // overlap row (first row of next strip): gy only -> also Hlast
        if (s != NSTRIP - 1) {
            const float* rp = img + (size_t)SROWS * IMW;
            const float4 v = *(const float4*)(rp + j0);
            float e0 = v.x - pv0, e1 = v.y - pv1, e2 = v.z - pv2, e3 = v.w - pv3;
            hl  = e0*e0 + e1*e1 + e2*e2 + e3*e3;
            aH += hl;
        }

        red[0][t] = aX;
        red[1][t] = aS;
        red[2][t] = aG + aG3;
        red[3][t] = aH;
        red[4][t] = hl;
        if ((t % 12) == 11) bnd[t / 12] = aG3;  // colG sum at column 48m+47
    }
    __syncthreads();

    float* out = g_seg + ((size_t)bc * NSTRIP + s) * SEGSTR;
    if (t < 5 * NSEG) {
        const int stat = t / NSEG, m = t % NSEG;
        float acc = 0.f;
        #pragma unroll
        for (int q = 0; q < 12; ++q) acc += red[stat][12 * m + q];
        out[stat * NSEG + m] = acc;
    } else if (t < 6 * NSEG) {
        out[t] = bnd[t - 5 * NSEG];   // stat 5 = bndG
    }
}

__global__ __launch_bounds__(512)
void niqe_pass23(const float* __restrict__ mu_p,
                 const float* __restrict__ cov_p,
                 float* __restrict__ out) {
    const int bc  = blockIdx.x;
    const int tid = threadIdx.x;
    __shared__ float r0[512], r1[512], r2[512];

    // ---- pass 2: per-patch stats, reduce to per-image feature sums ----
    float mu = 0.f, var = 0.f, gm = 0.f;
    if (tid < NPR * NPR) {
        const int pr = tid / NPR, pc = tid % NPR;
        const float* base = g_seg + ((size_t)bc * NSTRIP + 2 * pr) * SEGSTR;
        float X = 0.f, S = 0.f, G = 0.f, H = 0.f;
        #pragma unroll
        for (int s4 = 0; s4 < 4; ++s4) {
            const float* seg = base + s4 * SEGSTR;
            X += seg[0*NSEG + pc] + seg[0*NSEG + pc + 1];
            S += seg[1*NSEG + pc] + seg[1*NSEG + pc + 1];
            G += seg[2*NSEG + pc] + seg[2*NSEG + pc + 1] - seg[5*NSEG + pc + 1];
            H += seg[3*NSEG + pc] + seg[3*NSEG + pc + 1];
        }
        const float* seg3 = base + 3 * SEGSTR;
        H -= seg3[4*NSEG + pc] + seg3[4*NSEG + pc + 1];  // 95-row gy window
        mu  = X / 9216.0f;
        var = (S - X * X / 9216.0f) / 9215.0f;
        gm  = sqrtf((G + H) / 9120.0f);
    }
    r0[tid] = mu; r1[tid] = var; r2[tid] = gm;
    __syncthreads();
    #pragma unroll
    for (int off = 256; off; off >>= 1) {
        if (tid < off) {
            r0[tid] += r0[tid + off];
            r1[tid] += r1[tid + off];
            r2[tid] += r2[tid + off];
        }
        __syncthreads();
    }
    if (tid == 0) {
        g_feat[bc * 3 + 0] = r0[0];
        g_feat[bc * 3 + 1] = r1[0];
        g_feat[bc * 3 + 2] = r2[0];
    }

    // ---- last block runs pass 3 ----
    __shared__ unsigned int amLast;
    __threadfence();
    if (tid == 0) amLast = (atomicAdd(&g_ctr, 1u) == NBC - 1) ? 1u : 0u;
    __syncthreads();
    if (!amLast) return;
    if (tid == 0) g_ctr = 0;   // reset for next (graph-replayed) launch
    __threadfence();

    __shared__ float feats[8][12];
    __shared__ float A[12][24];
    __shared__ float fcol[12];
    __shared__ float piv;
    __shared__ float dist[8];

    if (tid < 96) {
        int b = tid / 12, fi = tid % 12;
        int s = fi / 4, c = fi % 4;   // feats layout: [mu(4), var(4), gm(4)]
        feats[b][fi] = __ldcg(&g_feat[(b * 4 + c) * 3 + s]) / 441.0f;
    }
    if (tid < 144) {
        int i = tid / 12, j = tid % 12;
        A[i][j]      = cov_p[i * 36 + j];
        A[i][12 + j] = (i == j) ? 1.0f : 0.0f;
    }
    __syncthreads();

    // Gauss-Jordan inverse of cov[:12,:12]
    for (int k = 0; k < 12; ++k) {
        if (tid == 0) piv = 1.0f / A[k][k];
        __syncthreads();
        if (tid < 24) A[k][tid] *= piv;
        __syncthreads();
        if (tid < 12) fcol[tid] = (tid == k) ? 0.0f : A[tid][k];
        __syncthreads();
        if (tid < 288) {
            int rr = tid / 24, cc = tid % 24;
            if (rr != k) A[rr][cc] -= fcol[rr] * A[k][cc];
        }
        __syncthreads();
    }

    if (tid < 8) {
        float d[12];
        #pragma unroll
        for (int i = 0; i < 12; ++i) d[i] = feats[tid][i] - mu_p[i];
        float q = 0.f;
        for (int i = 0; i < 12; ++i) {
            float t = 0.f;
            for (int j = 0; j < 12; ++j) t += A[i][12 + j] * d[j];
            q += d[i] * t;
        }
        dist[tid] = sqrtf(q);
    }
    __syncthreads();

    if (tid == 0) {
        float ssum = 0.f;
        for (int b = 0; b < 8; ++b) ssum += dist[b];
        out[0] = ssum * 0.125f;
    }
}

extern "C" void kernel_launch(void* const* d_in, const int* in_sizes, int n_in,
                              void* d_out, int out_size) {
    const float* x     = (const float*)d_in[0];
    const float* mu_p  = (const float*)d_in[1];
    const float* cov_p = (const float*)d_in[2];
    float* out = (float*)d_out;

    niqe_pass1<<<dim3(NSTRIP, NBC), P1_T>>>(x);
    niqe_pass23<<<NBC, 512>>>(mu_p, cov_p, out);
}

// round 9
// speedup vs baseline: 2.4884x; 1.0531x over previous
#include <cuda_runtime.h>
#include <cuda_bf16.h>
#include <math.h>

// NIQE-style patch statistics + Mahalanobis distance.
// x: (8,4,1056,1056) fp32. PATCH=96, STRIDE=48 -> 21x21 patches per image.
//
// Pass 1: per (b*c, 24-row strip), scalar per-thread accumulators; segment
//   (48-col) sums + bndG boundary column. (unchanged from R6)
// Pass 2 (+3 fused): 1 block/image, 448 threads; per-patch stats reduced via
//   warp shuffles (2 barriers). Last block (atomic counter) runs pass 3 in a
//   SINGLE WARP: row-per-lane Gauss-Jordan solve of cov[:12,:12] * Y = D via
//   shfl broadcasts -- zero block barriers in the serial chain.

#define IMW 1056
#define NSTRIP 44   // 1056 / 24
#define SROWS 24
#define NPR 21
#define NBC 32
#define P1_T 288
#define NF4 264     // 1056/4 float4-columns
#define NSEG 22     // 1056/48 segments
#define SEGSTR (6 * NSEG)   // per (bc,strip): X,X2,G,H,Hl,bndG
#define FULLM 0xffffffffu

__device__ float g_seg [NBC * NSTRIP * SEGSTR];
__device__ float g_feat[NBC * 3];
__device__ unsigned int g_ctr = 0;

__global__ __launch_bounds__(P1_T, 4)
void niqe_pass1(const float* __restrict__ x) {
    const int s   = blockIdx.x;   // strip 0..43
    const int bc  = blockIdx.y;   // image 0..31
    const int t   = threadIdx.x;

    __shared__ float red[5][NF4];
    __shared__ float bnd[NSEG];

    float aX = 0.f, aS = 0.f, aG = 0.f, aG3 = 0.f, aH = 0.f, hl = 0.f;

    if (t < NF4) {
        const int j0   = t * 4;
        const int offn = (t < NF4 - 1) ? 4 : 3;   // clamped: edge thread gets d3 = 0 exactly
        const float* img = x + (size_t)bc * IMW * IMW + (size_t)s * SROWS * IMW;
        float pv0, pv1, pv2, pv3;

        // row 0: x-stats + gx (no gy)
        {
            const float4 v = *(const float4*)(img + j0);
            const float vn = img[j0 + offn];
            aX += v.x + v.y + v.z + v.w;
            aS += v.x*v.x + v.y*v.y + v.z*v.z + v.w*v.w;
            float d0 = v.y - v.x, d1 = v.z - v.y, d2 = v.w - v.z, d3 = vn - v.w;
            aG  += d0*d0 + d1*d1 + d2*d2;
            aG3 += d3*d3;
            pv0 = v.x; pv1 = v.y; pv2 = v.z; pv3 = v.w;
        }
        // rows 1..23: all stats; unroll 8, unconditional loads
        #pragma unroll 8
        for (int i = 1; i < SROWS; ++i) {
            const float* rp = img + (size_t)i * IMW;
            const float4 v = *(const float4*)(rp + j0);
            const float vn = rp[j0 + offn];
            aX += v.x + v.y + v.z + v.w;
            aS += v.x*v.x + v.y*v.y + v.z*v.z + v.w*v.w;
            float e0 = v.x - pv0, e1 = v.y - pv1, e2 = v.z - pv2, e3 = v.w - pv3;
            aH += e0*e0 + e1*e1 + e2*e2 + e3*e3;
            float d0 = v.y - v.x, d1 = v.z - v.y, d2 = v.w - v.z, d3 = vn - v.w;
            aG  += d0*d0 + d1*d1 + d2*d2;
            aG3 += d3*d3;
            pv0 = v.x; pv1 = v.y; pv2 = v.z; pv3 = v.w;
        }
        // overlap row (first row of next strip): gy only -> also Hlast
        if (s != NSTRIP - 1) {
            const float* rp = img + (size_t)SROWS * IMW;
            const float4 v = *(const float4*)(rp + j0);
            float e0 = v.x - pv0, e1 = v.y - pv1, e2 = v.z - pv2, e3 = v.w - pv3;
            hl  = e0*e0 + e1*e1 + e2*e2 + e3*e3;
            aH += hl;
        }

        red[0][t] = aX;
        red[1][t] = aS;
        red[2][t] = aG + aG3;
        red[3][t] = aH;
        red[4][t] = hl;
        if ((t % 12) == 11) bnd[t / 12] = aG3;  // colG sum at column 48m+47
    }
    __syncthreads();

    float* out = g_seg + ((size_t)bc * NSTRIP + s) * SEGSTR;
    if (t < 5 * NSEG) {
        const int stat = t / NSEG, m = t % NSEG;
        float acc = 0.f;
        #pragma unroll
        for (int q = 0; q < 12; ++q) acc += red[stat][12 * m + q];
        out[stat * NSEG + m] = acc;
    } else if (t < 6 * NSEG) {
        out[t] = bnd[t - 5 * NSEG];   // stat 5 = bndG
    }
}

__global__ __launch_bounds__(448)
void niqe_pass23(const float* __restrict__ mu_p,
                 const float* __restrict__ cov_p,
                 float* __restrict__ out) {
    const int bc   = blockIdx.x;
    const int tid  = threadIdx.x;
    const int wid  = tid >> 5;
    const int lane = tid & 31;
    __shared__ float w0[14], w1[14], w2[14];

    // ---- pass 2: per-patch stats (441 threads), shuffle reductions ----
    float mu = 0.f, var = 0.f, gm = 0.f;
    if (tid < NPR * NPR) {
        const int pr = tid / NPR, pc = tid % NPR;
        const float* base = g_seg + ((size_t)bc * NSTRIP + 2 * pr) * SEGSTR;
        float X = 0.f, S = 0.f, G = 0.f, H = 0.f;
        #pragma unroll
        for (int s4 = 0; s4 < 4; ++s4) {
            const float* seg = base + s4 * SEGSTR;
            X += seg[0*NSEG + pc] + seg[0*NSEG + pc + 1];
            S += seg[1*NSEG + pc] + seg[1*NSEG + pc + 1];
            G += seg[2*NSEG + pc] + seg[2*NSEG + pc + 1] - seg[5*NSEG + pc + 1];
            H += seg[3*NSEG + pc] + seg[3*NSEG + pc + 1];
        }
        const float* seg3 = base + 3 * SEGSTR;
        H -= seg3[4*NSEG + pc] + seg3[4*NSEG + pc + 1];  // 95-row gy window
        mu  = X / 9216.0f;
        var = (S - X * X / 9216.0f) / 9215.0f;
        gm  = sqrtf((G + H) / 9120.0f);
    }
    #pragma unroll
    for (int off = 16; off; off >>= 1) {
        mu  += __shfl_xor_sync(FULLM, mu,  off);
        var += __shfl_xor_sync(FULLM, var, off);
        gm  += __shfl_xor_sync(FULLM, gm,  off);
    }
    if (lane == 0) { w0[wid] = mu; w1[wid] = var; w2[wid] = gm; }
    __syncthreads();
    if (wid == 0) {
        float a = (lane < 14) ? w0[lane] : 0.f;
        float b = (lane < 14) ? w1[lane] : 0.f;
        float c = (lane < 14) ? w2[lane] : 0.f;
        #pragma unroll
        for (int off = 8; off; off >>= 1) {
            a += __shfl_xor_sync(FULLM, a, off, 16);
            b += __shfl_xor_sync(FULLM, b, off, 16);
            c += __shfl_xor_sync(FULLM, c, off, 16);
        }
        if (lane == 0) {
            g_feat[bc * 3 + 0] = a;
            g_feat[bc * 3 + 1] = b;
            g_feat[bc * 3 + 2] = c;
        }
    }

    // ---- last block's warp 0 runs pass 3 (zero block barriers) ----
    __shared__ unsigned int amLast;
    __threadfence();
    if (tid == 0) amLast = (atomicAdd(&g_ctr, 1u) == NBC - 1) ? 1u : 0u;
    __syncthreads();
    if (!amLast) return;
    if (wid != 0) return;
    if (lane == 0) g_ctr = 0;   // reset for next (graph-replayed) launch

    // lane i (i<12) owns row i of [ cov(12x12) | D(12x8) ],
    // D[:,b] = feats[b] - mu_pristine. feats index fi = s*4 + c, bc = b*4+c.
    float a[12], r[8], d0[8];
    const int i = lane;
    if (i < 12) {
        #pragma unroll
        for (int j = 0; j < 12; ++j) a[j] = cov_p[i * 36 + j];
        const int s = i >> 2, c = i & 3;
        #pragma unroll
        for (int b = 0; b < 8; ++b) {
            float f = __ldcg(&g_feat[(b * 4 + c) * 3 + s]) / 441.0f;
            d0[b] = f - mu_p[i];
            r[b]  = d0[b];
        }
    } else {
        #pragma unroll
        for (int j = 0; j < 12; ++j) a[j] = 0.f;
        #pragma unroll
        for (int b = 0; b < 8; ++b) { r[b] = 0.f; d0[b] = 0.f; }
    }

    // Gauss-Jordan elimination (no row scaling): after 12 iterations each
    // row i has only its diagonal in A, so Y[i][b] = r[b] / a[i].
    #pragma unroll
    for (int k = 0; k < 12; ++k) {
        const float akk = __shfl_sync(FULLM, a[k], k);
        float f = a[k] / akk;
        if (i == k || i >= 12) f = 0.f;
        #pragma unroll
        for (int j = 0; j < 12; ++j) a[j] -= f * __shfl_sync(FULLM, a[j], k);
        #pragma unroll
        for (int b = 0; b < 8; ++b)  r[b] -= f * __shfl_sync(FULLM, r[b], k);
    }

    // q_b = sum_i d0[b] * y[b]  (lanes >= 12 contribute 0)
    float q[8];
    const float invd = (i < 12) ? (1.0f / a[i]) : 0.f;
    #pragma unroll
    for (int b = 0; b < 8; ++b) {
        float t = d0[b] * r[b] * invd;
        #pragma unroll
        for (int off = 16; off; off >>= 1)
            t += __shfl_xor_sync(FULLM, t, off);
        q[b] = t;
    }
    if (lane == 0) {
        float ssum = 0.f;
        #pragma unroll
        for (int b = 0; b < 8; ++b) ssum += sqrtf(q[b]);
        out[0] = ssum * 0.125f;
    }
}

extern "C" void kernel_launch(void* const* d_in, const int* in_sizes, int n_in,
                              void* d_out, int out_size) {
    const float* x     = (const float*)d_in[0];
    const float* mu_p  = (const float*)d_in[1];
    const float* cov_p = (const float*)d_in[2];
    float* out = (float*)d_out;

    niqe_pass1<<<dim3(NSTRIP, NBC), P1_T>>>(x);
    niqe_pass23<<<NBC, 448>>>(mu_p, cov_p, out);
}